// round 5
// baseline (speedup 1.0000x reference)
#include <cuda_runtime.h>
#include <cstdint>

// ============================================================================
// QuantumFeedForward: out = relu(quant(x@W1 + b1)) @ W2 + b2   (fp32 in/out)
//
// R4 (= R3 re-bench after infra failure): legacy tf32 mma.sync (sm_100 base
// target — tcgen05 is ptxas-gated off), with ALL tf32 conversions hoisted out
// of the hot loop:
//   prepass: RNA-round x -> g_xr, W1 -> g_w1r, W2 -> g_w2r (bit-exact tf32)
//   K1: g_act = relu(quant(g_xr @ W1r + b1))   [stored pre-rounded to tf32]
//   K2: out   = g_act @ W2r + b2
// Hot loop feeds raw fp32 bits of pre-rounded values to mma (truncation = id).
// CTA 128x128x32, 8 warps (2x4) at 64x32, m16n8k8 tf32, 2-stage cp.async,
// padded smem (A stride%32==4, B stride%32==8 -> conflict-free frag loads).
// ============================================================================

#define M_TOT   8192
#define DFF     4096
#define DMODEL  1024

__device__ float g_act[(size_t)M_TOT * DFF];     // 128 MB
__device__ float g_xr [(size_t)M_TOT * DMODEL];  // 32 MB
__device__ float g_w1r[(size_t)DMODEL * DFF];    // 16 MB
__device__ float g_w2r[(size_t)DFF * DMODEL];    // 16 MB

#define A_STRIDE 36   // 32+4: stride mod 32 == 4
#define B_STRIDE 136  // 128+8: stride mod 32 == 8
#define AS_FLOATS (2 * 128 * A_STRIDE)   // 9216
#define BS_FLOATS (2 * 32 * B_STRIDE)    // 8704
#define SMEM_BYTES ((AS_FLOATS + BS_FLOATS) * 4)  // 71680

__device__ __forceinline__ uint32_t f2tf32(float x) {
    uint32_t r;
    asm("cvt.rna.tf32.f32 %0, %1;" : "=r"(r) : "f"(x));
    return r;
}

__device__ __forceinline__ void cp_async16(void* smem_dst, const void* gmem_src) {
    uint32_t s = (uint32_t)__cvta_generic_to_shared(smem_dst);
    asm volatile("cp.async.cg.shared.global [%0], [%1], 16;\n" :: "r"(s), "l"(gmem_src));
}
__device__ __forceinline__ void cp_commit() {
    asm volatile("cp.async.commit_group;\n");
}
template <int N>
__device__ __forceinline__ void cp_wait() {
    asm volatile("cp.async.wait_group %0;\n" :: "n"(N));
}

__device__ __forceinline__ void mma_tf32(float acc[4],
                                         const uint32_t a[4], const uint32_t b[2]) {
    asm volatile(
        "mma.sync.aligned.m16n8k8.row.col.f32.tf32.tf32.f32 "
        "{%0,%1,%2,%3}, {%4,%5,%6,%7}, {%8,%9}, {%0,%1,%2,%3};"
        : "+f"(acc[0]), "+f"(acc[1]), "+f"(acc[2]), "+f"(acc[3])
        : "r"(a[0]), "r"(a[1]), "r"(a[2]), "r"(a[3]), "r"(b[0]), "r"(b[1]));
}

// ============================================================================
// Prepass: RNA-round fp32 -> tf32-representable fp32 (bulk, vectorized)
// ============================================================================
__global__ void round_copy(const float4* __restrict__ in, float4* __restrict__ out, int n4) {
    int i = blockIdx.x * blockDim.x + threadIdx.x;
    if (i < n4) {
        float4 v = in[i];
        v.x = __uint_as_float(f2tf32(v.x));
        v.y = __uint_as_float(f2tf32(v.y));
        v.z = __uint_as_float(f2tf32(v.z));
        v.w = __uint_as_float(f2tf32(v.w));
        out[i] = v;
    }
}

// ============================================================================
// Main fused GEMM
// QUANT=true:  A=g_xr,  B=g_w1r, C=g_act, epi = bias+quantum+relu (+round)
// QUANT=false: A=g_act, B=g_w2r, C=out,   epi = bias
// ============================================================================
template <bool QUANT, int N, int K>
__global__ __launch_bounds__(256, 2) void qff_gemm(
    const float* __restrict__ bias,
    const float* __restrict__ theta,
    const float* __restrict__ w_real,
    const float* __restrict__ w_imag,
    float* __restrict__ C_param)
{
    extern __shared__ float smem[];
    float* As = smem;                 // [2][128][A_STRIDE]
    float* Bs = smem + AS_FLOATS;     // [2][32][B_STRIDE]

    const float* A = QUANT ? g_xr  : g_act;
    const float* Bw = QUANT ? g_w1r : g_w2r;
    float*       C = QUANT ? g_act : C_param;

    const int tid  = threadIdx.x;
    const int warp = tid >> 5;
    const int lane = tid & 31;
    const int wm = warp >> 2;         // 0..1  (M dir, 64 rows each)
    const int wn = warp & 3;          // 0..3  (N dir, 32 cols each)
    const int gi = lane >> 2;         // 0..7
    const int ci = lane & 3;          // 0..3

    const int bm = blockIdx.y * 128;
    const int bn = blockIdx.x * 128;

    const float* Ab = A + (size_t)bm * K;
    const float* Bb = Bw + bn;

    float acc[4][4][4];
#pragma unroll
    for (int i = 0; i < 4; i++)
#pragma unroll
        for (int j = 0; j < 4; j++)
#pragma unroll
            for (int r = 0; r < 4; r++) acc[i][j][r] = 0.0f;

    const int a_row = tid >> 3;            // 0..31, +32*p
    const int a_c4  = (tid & 7) * 4;
    const int b_row = tid >> 5;            // 0..7, +8*p
    const int b_c4  = (tid & 31) * 4;

    auto load_tiles = [&](int kt, int buf) {
        const int k0 = kt * 32;
#pragma unroll
        for (int p = 0; p < 4; p++) {
            const int r = a_row + p * 32;
            cp_async16(&As[(buf * 128 + r) * A_STRIDE + a_c4],
                       Ab + (size_t)r * K + k0 + a_c4);
        }
#pragma unroll
        for (int p = 0; p < 4; p++) {
            const int r = b_row + p * 8;
            cp_async16(&Bs[(buf * 32 + r) * B_STRIDE + b_c4],
                       Bb + (size_t)(k0 + r) * N + b_c4);
        }
        cp_commit();
    };

    constexpr int KT = K / 32;

    load_tiles(0, 0);

#pragma unroll 1
    for (int kt = 0; kt < KT; ++kt) {
        const int cur = kt & 1;
        if (kt + 1 < KT) {
            load_tiles(kt + 1, cur ^ 1);
            cp_wait<1>();
        } else {
            cp_wait<0>();
        }
        __syncthreads();

        // values in smem are pre-rounded to tf32; feed raw bits (no cvt)
        const uint32_t* As_t = reinterpret_cast<const uint32_t*>(&As[cur * 128 * A_STRIDE]);
        const uint32_t* Bs_t = reinterpret_cast<const uint32_t*>(&Bs[cur * 32 * B_STRIDE]);

#pragma unroll
        for (int kk = 0; kk < 4; kk++) {
            const int kb = kk * 8;
            uint32_t afr[4][4];
            uint32_t bfr[4][2];
#pragma unroll
            for (int mi = 0; mi < 4; mi++) {
                const uint32_t* ap = &As_t[(wm * 64 + mi * 16 + gi) * A_STRIDE + kb + ci];
                afr[mi][0] = ap[0];
                afr[mi][1] = ap[8 * A_STRIDE];
                afr[mi][2] = ap[4];
                afr[mi][3] = ap[8 * A_STRIDE + 4];
            }
#pragma unroll
            for (int ni = 0; ni < 4; ni++) {
                const uint32_t* bp = &Bs_t[(kb + ci) * B_STRIDE + wn * 32 + ni * 8 + gi];
                bfr[ni][0] = bp[0];
                bfr[ni][1] = bp[4 * B_STRIDE];
            }
#pragma unroll
            for (int mi = 0; mi < 4; mi++)
#pragma unroll
                for (int ni = 0; ni < 4; ni++)
                    mma_tf32(acc[mi][ni], afr[mi], bfr[ni]);
        }
        __syncthreads();
    }

    // ---------------- epilogue ----------------
#pragma unroll
    for (int mi = 0; mi < 4; mi++) {
        const int r0 = bm + wm * 64 + mi * 16 + gi;
#pragma unroll
        for (int ni = 0; ni < 4; ni++) {
            const int col = bn + wn * 32 + ni * 8 + ci * 2;
#pragma unroll
            for (int half = 0; half < 2; half++) {
                const int r = r0 + half * 8;
                float v0 = acc[mi][ni][half * 2 + 0];
                float v1 = acc[mi][ni][half * 2 + 1];
                if (QUANT) {
                    {
                        float h = v0 + __ldg(&bias[col]);
                        float th = __ldg(&theta[col]);
                        float wi = __ldg(&w_imag[col]);
                        float s, cth; __sincosf(th, &s, &cth);
                        float qp = cth * __ldg(&w_real[col]) + s * wi;
                        float im = wi * __sinf(th + 0.1f * h);
                        v0 = fmaxf(h + qp * im * 0.1f, 0.0f);
                        v0 = __uint_as_float(f2tf32(v0));   // pre-round for GEMM2
                    }
                    {
                        float h = v1 + __ldg(&bias[col + 1]);
                        float th = __ldg(&theta[col + 1]);
                        float wi = __ldg(&w_imag[col + 1]);
                        float s, cth; __sincosf(th, &s, &cth);
                        float qp = cth * __ldg(&w_real[col + 1]) + s * wi;
                        float im = wi * __sinf(th + 0.1f * h);
                        v1 = fmaxf(h + qp * im * 0.1f, 0.0f);
                        v1 = __uint_as_float(f2tf32(v1));
                    }
                } else {
                    v0 += __ldg(&bias[col]);
                    v1 += __ldg(&bias[col + 1]);
                }
                float2 st = make_float2(v0, v1);
                *reinterpret_cast<float2*>(&C[(size_t)r * N + col]) = st;
            }
        }
    }
}

extern "C" void kernel_launch(void* const* d_in, const int* in_sizes, int n_in,
                              void* d_out, int out_size) {
    (void)in_sizes; (void)n_in; (void)out_size;
    const float* x  = (const float*)d_in[0];
    const float* W1 = (const float*)d_in[1];
    const float* b1 = (const float*)d_in[2];
    const float* th = (const float*)d_in[3];
    const float* wr = (const float*)d_in[4];
    const float* wi = (const float*)d_in[5];
    const float* W2 = (const float*)d_in[6];
    const float* b2 = (const float*)d_in[7];
    float* out = (float*)d_out;

    float* xr;  cudaGetSymbolAddress((void**)&xr,  g_xr);
    float* w1r; cudaGetSymbolAddress((void**)&w1r, g_w1r);
    float* w2r; cudaGetSymbolAddress((void**)&w2r, g_w2r);

    // prepass: bulk RNA-round inputs so the GEMM hot loops are cvt-free
    {
        int n4 = M_TOT * DMODEL / 4;
        round_copy<<<(n4 + 1023) / 1024, 1024>>>((const float4*)x, (float4*)xr, n4);
    }
    {
        int n4 = DMODEL * DFF / 4;
        round_copy<<<(n4 + 1023) / 1024, 1024>>>((const float4*)W1, (float4*)w1r, n4);
        round_copy<<<(n4 + 1023) / 1024, 1024>>>((const float4*)W2, (float4*)w2r, n4);
    }

    auto k1 = qff_gemm<true,  DFF,    DMODEL>;
    auto k2 = qff_gemm<false, DMODEL, DFF>;
    cudaFuncSetAttribute((const void*)k1, cudaFuncAttributeMaxDynamicSharedMemorySize, SMEM_BYTES);
    cudaFuncSetAttribute((const void*)k2, cudaFuncAttributeMaxDynamicSharedMemorySize, SMEM_BYTES);

    dim3 grid1(DFF / 128, M_TOT / 128);     // (32, 64)
    dim3 grid2(DMODEL / 128, M_TOT / 128);  // (8, 64)

    k1<<<grid1, 256, SMEM_BYTES>>>(b1, th, wr, wi, nullptr);
    k2<<<grid2, 256, SMEM_BYTES>>>(b2, nullptr, nullptr, nullptr, out);
}